// round 1
// baseline (speedup 1.0000x reference)
#include <cuda_runtime.h>
#include <cuda_bf16.h>
#include <math.h>

#define B_ 4
#define T_ 1024
#define D_ 1024
#define H_ 16
#define DK_ 64
#define BTD (B_*T_*D_)

// ---------------- scratch (device globals; no allocation allowed) ----------------
__device__ float g_Q[BTD];      // [B,H,T,DK]
__device__ float g_K[BTD];      // [B,H,T,DK]
__device__ float g_V[BTD];      // [B,H,T,DK]
__device__ float g_attn[BTD];   // [B,T,D]
__device__ float g_c[B_];
__device__ float g_tau[B_];
__device__ float g_vmean[B_*H_*DK_];

// ---------------- GEMM: Y = X @ W^T + bias ----------------
// X:[M,K] row-major, W:[N,K] row-major. BM=BN=128, BK=8, 256 threads, 8x8 micro-tile.
// MODE 0: Y[m*N+n]   MODE 1: head-split  Y[((b*H+h)*T+t)*DK+dk]
template<int MODE>
__global__ void __launch_bounds__(256)
sgemm_bias(const float* __restrict__ X, const float* __restrict__ W,
           const float* __restrict__ bias, float* __restrict__ Y,
           int M, int N, int K)
{
    __shared__ float Xs[8][128];
    __shared__ float Ws[8][128];

    const int tid = threadIdx.x;
    const int bm = blockIdx.y * 128;
    const int bn = blockIdx.x * 128;

    const int lr = tid >> 1;          // 0..127
    const int lc = (tid & 1) * 4;     // 0 or 4
    const float* Xg = X + (size_t)(bm + lr) * K + lc;
    const float* Wg = W + (size_t)(bn + lr) * K + lc;

    float acc[8][8];
#pragma unroll
    for (int i = 0; i < 8; i++)
#pragma unroll
        for (int j = 0; j < 8; j++) acc[i][j] = 0.f;

    const int ty = tid >> 4;   // 0..15
    const int tx = tid & 15;   // 0..15

    for (int k0 = 0; k0 < K; k0 += 8) {
        float4 xa = *(const float4*)(Xg + k0);
        float4 wa = *(const float4*)(Wg + k0);
        Xs[lc+0][lr] = xa.x; Xs[lc+1][lr] = xa.y; Xs[lc+2][lr] = xa.z; Xs[lc+3][lr] = xa.w;
        Ws[lc+0][lr] = wa.x; Ws[lc+1][lr] = wa.y; Ws[lc+2][lr] = wa.z; Ws[lc+3][lr] = wa.w;
        __syncthreads();
#pragma unroll
        for (int kk = 0; kk < 8; kk++) {
            float rm[8], rn[8];
#pragma unroll
            for (int i = 0; i < 8; i++) rm[i] = Xs[kk][ty*8 + i];
#pragma unroll
            for (int j = 0; j < 8; j++) rn[j] = Ws[kk][tx*8 + j];
#pragma unroll
            for (int i = 0; i < 8; i++)
#pragma unroll
                for (int j = 0; j < 8; j++)
                    acc[i][j] += rm[i] * rn[j];
        }
        __syncthreads();
    }

#pragma unroll
    for (int i = 0; i < 8; i++) {
        const int m = bm + ty*8 + i;
#pragma unroll
        for (int j = 0; j < 8; j++) {
            const int n = bn + tx*8 + j;
            const float v = acc[i][j] + bias[n];
            if (MODE == 0) {
                Y[(size_t)m * N + n] = v;
            } else {
                const int b  = m >> 10;      // m / T
                const int t  = m & 1023;
                const int h  = n >> 6;       // n / DK
                const int dk = n & 63;
                Y[((size_t)(b*H_ + h) * T_ + t) * DK_ + dk] = v;
            }
        }
    }
}

// ---------------- gate: c, tau, u per batch ----------------
__global__ void gate_kernel(const float* __restrict__ Wg1, const float* __restrict__ bg1,
                            const float* __restrict__ Wg2, const float* __restrict__ bg2,
                            float* __restrict__ u_out)
{
    const int b = blockIdx.x;
    const int tid = threadIdx.x;
    __shared__ float sh1[256], sh2[256];
    float s1 = 0.f, s2 = 0.f;
    for (int d = tid; d < D_; d += 256) {
        const int h  = d >> 6;
        const int dk = d & 63;
        // context = Q[b, h, t=0, dk]
        const float ctx = g_Q[((size_t)(b*H_ + h) * T_ + 0) * DK_ + dk];
        s1 += ctx * Wg1[d];
        s2 += ctx * Wg2[d];
    }
    sh1[tid] = s1; sh2[tid] = s2;
    __syncthreads();
    for (int off = 128; off > 0; off >>= 1) {
        if (tid < off) { sh1[tid] += sh1[tid+off]; sh2[tid] += sh2[tid+off]; }
        __syncthreads();
    }
    if (tid == 0) {
        const float a1 = sh1[0] + bg1[0];
        const float a2 = sh2[0] + bg2[0];
        const float q1 = 1.f / (1.f + expf(-a1));
        const float q2 = 1.f / (1.f + expf(-a2));
        float c = q1 * q2;
        c = fminf(fmaxf(c, 1e-8f), 1.0f);
        g_c[b]   = c;
        g_tau[b] = (c < 0.3f) ? (1.0f / c) : 1.0f;
        if (u_out) u_out[b] = 1.0f - c;
    }
}

// ---------------- V mean over time ----------------
__global__ void vmean_kernel()
{
    const int bh = blockIdx.x;       // 0..63
    const int d  = threadIdx.x;      // 0..63
    const float* Vp = g_V + (size_t)bh * T_ * DK_;
    float s = 0.f;
    for (int t = 0; t < T_; t++) s += Vp[t * DK_ + d];
    g_vmean[bh * DK_ + d] = s * (1.0f / (float)T_);
}

// ---------------- flash attention + epistemic gating ----------------
// grid: (B*H, T/128), block: 128 threads; thread owns one q-row.
__global__ void __launch_bounds__(128)
flash_attn_kernel()
{
    const int bh = blockIdx.x;
    const int b  = bh >> 4;
    const int h  = bh & 15;
    const int q0 = blockIdx.y * 128;
    const int tid = threadIdx.x;

    __shared__ float Ks[64 * 64];
    __shared__ float Vs[64 * 64];

    const float* Qp = g_Q + ((size_t)bh * T_ + q0) * DK_;
    const float* Kp = g_K + (size_t)bh * T_ * DK_;
    const float* Vp = g_V + (size_t)bh * T_ * DK_;

    const float tau   = g_tau[b];
    const float scale = 0.125f / tau;   // 1/sqrt(64)/tau

    // load my q row into registers
    float q[64];
    {
        const float4* q4 = (const float4*)(Qp + (size_t)tid * DK_);
#pragma unroll
        for (int i = 0; i < 16; i++) {
            float4 v = q4[i];
            q[4*i+0] = v.x; q[4*i+1] = v.y; q[4*i+2] = v.z; q[4*i+3] = v.w;
        }
    }

    float o[64];
#pragma unroll
    for (int d = 0; d < 64; d++) o[d] = 0.f;
    float m = -1e30f, l = 0.f;

    for (int kt = 0; kt < T_ / 64; kt++) {
        // cooperative load of K/V tile (64x64), coalesced float4
        {
            const float4* kg = (const float4*)(Kp + (size_t)kt * 64 * DK_);
            const float4* vg = (const float4*)(Vp + (size_t)kt * 64 * DK_);
            float4* ks4 = (float4*)Ks;
            float4* vs4 = (float4*)Vs;
#pragma unroll
            for (int i = 0; i < 8; i++) {
                ks4[tid + i*128] = kg[tid + i*128];
                vs4[tid + i*128] = vg[tid + i*128];
            }
        }
        __syncthreads();

#pragma unroll 2
        for (int kk = 0; kk < 64; kk++) {
            const float4* k4 = (const float4*)(Ks + kk * 64);
            float s = 0.f;
#pragma unroll
            for (int i = 0; i < 16; i++) {
                float4 kv = k4[i];
                s += q[4*i+0]*kv.x + q[4*i+1]*kv.y + q[4*i+2]*kv.z + q[4*i+3]*kv.w;
            }
            s *= scale;
            if (s > m) {
                const float corr = __expf(m - s);
                m = s;
                l *= corr;
#pragma unroll
                for (int d = 0; d < 64; d++) o[d] *= corr;
            }
            const float p = __expf(s - m);
            l += p;
            const float4* v4 = (const float4*)(Vs + kk * 64);
#pragma unroll
            for (int i = 0; i < 16; i++) {
                float4 vv = v4[i];
                o[4*i+0] += p * vv.x;
                o[4*i+1] += p * vv.y;
                o[4*i+2] += p * vv.z;
                o[4*i+3] += p * vv.w;
            }
        }
        __syncthreads();
    }

    // gating epilogue: attn = c * (o/l) + (1-c) * vmean
    const float c    = g_c[b];
    const float cl   = c / l;
    const float omc  = 1.0f - c;
    const float* vm  = g_vmean + bh * DK_;
    float* outp = g_attn + ((size_t)(b * T_) + q0 + tid) * D_ + h * DK_;
    float4* out4 = (float4*)outp;
#pragma unroll
    for (int i = 0; i < 16; i++) {
        float4 r;
        r.x = o[4*i+0]*cl + omc*vm[4*i+0];
        r.y = o[4*i+1]*cl + omc*vm[4*i+1];
        r.z = o[4*i+2]*cl + omc*vm[4*i+2];
        r.w = o[4*i+3]*cl + omc*vm[4*i+3];
        out4[i] = r;
    }
}

// ---------------- launch ----------------
extern "C" void kernel_launch(void* const* d_in, const int* in_sizes, int n_in,
                              void* d_out, int out_size)
{
    const float* x   = (const float*)d_in[0];
    const float* Wq  = (const float*)d_in[1];
    const float* bq  = (const float*)d_in[2];
    const float* Wk  = (const float*)d_in[3];
    const float* bk  = (const float*)d_in[4];
    const float* Wv  = (const float*)d_in[5];
    const float* bv  = (const float*)d_in[6];
    const float* Wo  = (const float*)d_in[7];
    const float* bo  = (const float*)d_in[8];
    const float* Wg1 = (const float*)d_in[9];
    const float* bg1 = (const float*)d_in[10];
    const float* Wg2 = (const float*)d_in[11];
    const float* bg2 = (const float*)d_in[12];
    float* out = (float*)d_out;

    float *pQ, *pK, *pV, *pAttn;
    cudaGetSymbolAddress((void**)&pQ,    g_Q);
    cudaGetSymbolAddress((void**)&pK,    g_K);
    cudaGetSymbolAddress((void**)&pV,    g_V);
    cudaGetSymbolAddress((void**)&pAttn, g_attn);

    const int M = B_ * T_, N = D_, K = D_;
    dim3 gemm_grid(N / 128, M / 128);   // (8, 32)

    // Q/K/V projections -> head-split layout
    sgemm_bias<1><<<gemm_grid, 256>>>(x, Wq, bq, pQ, M, N, K);
    sgemm_bias<1><<<gemm_grid, 256>>>(x, Wk, bk, pK, M, N, K);
    sgemm_bias<1><<<gemm_grid, 256>>>(x, Wv, bv, pV, M, N, K);

    // gate (c, tau, u)
    float* u_out = (out_size >= BTD + B_) ? (out + (out_size - B_)) : nullptr;
    gate_kernel<<<B_, 256>>>(Wg1, bg1, Wg2, bg2, u_out);

    // V mean over time
    vmean_kernel<<<B_ * H_, DK_>>>();

    // flash attention with epistemic gating
    dim3 attn_grid(B_ * H_, T_ / 128);
    flash_attn_kernel<<<attn_grid, 128>>>();

    // output projection
    sgemm_bias<0><<<gemm_grid, 256>>>(pAttn, Wo, bo, out, M, N, K);
}

// round 3
// speedup vs baseline: 1.0650x; 1.0650x over previous
#include <cuda_runtime.h>
#include <cuda_bf16.h>
#include <math.h>

#define B_ 4
#define T_ 1024
#define D_ 1024
#define H_ 16
#define DK_ 64
#define BTD (B_*T_*D_)

// ---------------- scratch (device globals; no allocation allowed) ----------------
__device__ float g_Q[BTD];      // [B,H,T,DK]
__device__ float g_K[BTD];      // [B,H,T,DK]
__device__ float g_V[BTD];      // [B,H,T,DK]
__device__ float g_attn[BTD];   // [B,T,D]
__device__ float g_c[B_];
__device__ float g_tau[B_];
__device__ float g_vmean[B_*H_*DK_];

// ---------------- tf32 helpers ----------------
__device__ __forceinline__ void split_tf32(float x, float& hi, float& lo) {
    unsigned h;
    asm("cvt.rna.tf32.f32 %0, %1;" : "=r"(h) : "f"(x));
    hi = __uint_as_float(h);
    float r = x - hi;
    unsigned l;
    asm("cvt.rna.tf32.f32 %0, %1;" : "=r"(l) : "f"(r));
    lo = __uint_as_float(l);
}

__device__ __forceinline__ void mma_tf32(float c[4], const unsigned a[4], const unsigned b[2]) {
    asm volatile(
        "mma.sync.aligned.m16n8k8.row.col.f32.tf32.tf32.f32 "
        "{%0,%1,%2,%3}, {%4,%5,%6,%7}, {%8,%9}, {%0,%1,%2,%3};"
        : "+f"(c[0]), "+f"(c[1]), "+f"(c[2]), "+f"(c[3])
        : "r"(a[0]), "r"(a[1]), "r"(a[2]), "r"(a[3]), "r"(b[0]), "r"(b[1]));
}

// ---------------- 3xTF32 GEMM: Y = X @ W^T + bias ----------------
// X:[M,K] row-major, W:[N,K] row-major. BM=BN=128, BK=16, 256 threads (8 warps).
// Warp tile 32x64 (warp_m = wid&3, warp_n = wid>>2).
// MODE 0: Y[m*N+n]   MODE 1: head-split  Y[((b*H+h)*T+t)*DK+dk]
#define SM_STRIDE 20   // 16 + 4 pad -> conflict-free for frag access pattern

template<int MODE>
__global__ void __launch_bounds__(256)
gemm_tf32(const float* __restrict__ X, const float* __restrict__ W,
          const float* __restrict__ bias, float* __restrict__ Y,
          int M, int N, int K)
{
    __shared__ float Xh[128][SM_STRIDE], Xl[128][SM_STRIDE];
    __shared__ float Wh[128][SM_STRIDE], Wl[128][SM_STRIDE];

    const int tid  = threadIdx.x;
    const int lane = tid & 31;
    const int wid  = tid >> 5;
    const int wm   = wid & 3;          // 0..3 -> 32-row slab
    const int wn   = wid >> 2;         // 0..1 -> 64-col slab
    const int bm   = blockIdx.y * 128;
    const int bn   = blockIdx.x * 128;

    const int lr = lane >> 2;          // 0..7
    const int lc = lane & 3;           // 0..3

    float C[2][8][4];
#pragma unroll
    for (int mt = 0; mt < 2; mt++)
#pragma unroll
        for (int nt = 0; nt < 8; nt++)
#pragma unroll
            for (int j = 0; j < 4; j++) C[mt][nt][j] = 0.f;

    // prefetch first chunk (each thread: 2 float4 from X, 2 from W)
    float4 xr[2], wr[2];
#pragma unroll
    for (int i = 0; i < 2; i++) {
        const int idx = tid + i * 256;
        const int r = idx >> 2, cg = (idx & 3) * 4;
        xr[i] = *(const float4*)&X[(size_t)(bm + r) * K + cg];
        wr[i] = *(const float4*)&W[(size_t)(bn + r) * K + cg];
    }

    for (int k0 = 0; k0 < K; k0 += 16) {
        // write current chunk to smem (split hi/lo)
#pragma unroll
        for (int i = 0; i < 2; i++) {
            const int idx = tid + i * 256;
            const int r = idx >> 2, cg = (idx & 3) * 4;
            float vx[4] = { xr[i].x, xr[i].y, xr[i].z, xr[i].w };
            float vw[4] = { wr[i].x, wr[i].y, wr[i].z, wr[i].w };
#pragma unroll
            for (int j = 0; j < 4; j++) {
                float h, l;
                split_tf32(vx[j], h, l);
                Xh[r][cg + j] = h; Xl[r][cg + j] = l;
                split_tf32(vw[j], h, l);
                Wh[r][cg + j] = h; Wl[r][cg + j] = l;
            }
        }
        __syncthreads();

        // prefetch next chunk
        if (k0 + 16 < K) {
#pragma unroll
            for (int i = 0; i < 2; i++) {
                const int idx = tid + i * 256;
                const int r = idx >> 2, cg = (idx & 3) * 4;
                xr[i] = *(const float4*)&X[(size_t)(bm + r) * K + k0 + 16 + cg];
                wr[i] = *(const float4*)&W[(size_t)(bn + r) * K + k0 + 16 + cg];
            }
        }

        // two k-steps of 8
#pragma unroll
        for (int ks = 0; ks < 2; ks++) {
            const int kb = ks * 8;
            unsigned Ah[2][4], Al[2][4];
#pragma unroll
            for (int mt = 0; mt < 2; mt++) {
                const int rb = wm * 32 + mt * 16 + lr;
                const int kc = kb + lc;
                Ah[mt][0] = __float_as_uint(Xh[rb    ][kc    ]);
                Ah[mt][1] = __float_as_uint(Xh[rb + 8][kc    ]);
                Ah[mt][2] = __float_as_uint(Xh[rb    ][kc + 4]);
                Ah[mt][3] = __float_as_uint(Xh[rb + 8][kc + 4]);
                Al[mt][0] = __float_as_uint(Xl[rb    ][kc    ]);
                Al[mt][1] = __float_as_uint(Xl[rb + 8][kc    ]);
                Al[mt][2] = __float_as_uint(Xl[rb    ][kc + 4]);
                Al[mt][3] = __float_as_uint(Xl[rb + 8][kc + 4]);
            }
            unsigned Bh[8][2], Bl[8][2];
#pragma unroll
            for (int nt = 0; nt < 8; nt++) {
                const int nb = wn * 64 + nt * 8 + lr;
                const int kc = kb + lc;
                Bh[nt][0] = __float_as_uint(Wh[nb][kc    ]);
                Bh[nt][1] = __float_as_uint(Wh[nb][kc + 4]);
                Bl[nt][0] = __float_as_uint(Wl[nb][kc    ]);
                Bl[nt][1] = __float_as_uint(Wl[nb][kc + 4]);
            }
#pragma unroll
            for (int mt = 0; mt < 2; mt++)
#pragma unroll
                for (int nt = 0; nt < 8; nt++) {
                    mma_tf32(C[mt][nt], Al[mt], Bh[nt]);   // lo*hi
                    mma_tf32(C[mt][nt], Ah[mt], Bl[nt]);   // hi*lo
                    mma_tf32(C[mt][nt], Ah[mt], Bh[nt]);   // hi*hi
                }
        }
        __syncthreads();
    }

    // epilogue: bias add + store
#pragma unroll
    for (int mt = 0; mt < 2; mt++) {
#pragma unroll
        for (int nt = 0; nt < 8; nt++) {
            const int row = bm + wm * 32 + mt * 16 + lr;
            const int col = bn + wn * 64 + nt * 8 + lc * 2;
            const float b0 = bias[col], b1 = bias[col + 1];
#pragma unroll
            for (int half = 0; half < 2; half++) {
                const int m = row + half * 8;
                const float v0 = C[mt][nt][half * 2 + 0] + b0;
                const float v1 = C[mt][nt][half * 2 + 1] + b1;
                if (MODE == 0) {
                    float2* p = (float2*)&Y[(size_t)m * N + col];
                    *p = make_float2(v0, v1);
                } else {
                    const int b  = m >> 10;
                    const int t  = m & 1023;
                    const int h  = col >> 6;
                    const int dk = col & 63;
                    float2* p = (float2*)&g_Q[0];  // placeholder type; real below
                    (void)p;
                    float2* q = (float2*)&Y[((size_t)(b * H_ + h) * T_ + t) * DK_ + dk];
                    *q = make_float2(v0, v1);
                }
            }
        }
    }
}

// ---------------- gate: c, tau, u per batch ----------------
__global__ void gate_kernel(const float* __restrict__ Wg1, const float* __restrict__ bg1,
                            const float* __restrict__ Wg2, const float* __restrict__ bg2,
                            float* __restrict__ u_out)
{
    const int b = blockIdx.x;
    const int tid = threadIdx.x;
    __shared__ float sh1[256], sh2[256];
    float s1 = 0.f, s2 = 0.f;
    for (int d = tid; d < D_; d += 256) {
        const int h  = d >> 6;
        const int dk = d & 63;
        const float ctx = g_Q[((size_t)(b*H_ + h) * T_ + 0) * DK_ + dk];
        s1 += ctx * Wg1[d];
        s2 += ctx * Wg2[d];
    }
    sh1[tid] = s1; sh2[tid] = s2;
    __syncthreads();
    for (int off = 128; off > 0; off >>= 1) {
        if (tid < off) { sh1[tid] += sh1[tid+off]; sh2[tid] += sh2[tid+off]; }
        __syncthreads();
    }
    if (tid == 0) {
        const float a1 = sh1[0] + bg1[0];
        const float a2 = sh2[0] + bg2[0];
        const float q1 = 1.f / (1.f + expf(-a1));
        const float q2 = 1.f / (1.f + expf(-a2));
        float c = q1 * q2;
        c = fminf(fmaxf(c, 1e-8f), 1.0f);
        g_c[b]   = c;
        g_tau[b] = (c < 0.3f) ? (1.0f / c) : 1.0f;
        if (u_out) u_out[b] = 1.0f - c;
    }
}

// ---------------- V mean over time ----------------
__global__ void vmean_kernel()
{
    const int bh = blockIdx.x;       // 0..63
    const int d  = threadIdx.x;      // 0..63
    const float* Vp = g_V + (size_t)bh * T_ * DK_;
    float s = 0.f;
    for (int t = 0; t < T_; t++) s += Vp[t * DK_ + d];
    g_vmean[bh * DK_ + d] = s * (1.0f / (float)T_);
}

// ---------------- flash attention + epistemic gating ----------------
__global__ void __launch_bounds__(128)
flash_attn_kernel()
{
    const int bh = blockIdx.x;
    const int b  = bh >> 4;
    const int h  = bh & 15;
    const int q0 = blockIdx.y * 128;
    const int tid = threadIdx.x;

    __shared__ float Ks[64 * 64];
    __shared__ float Vs[64 * 64];

    const float* Qp = g_Q + ((size_t)bh * T_ + q0) * DK_;
    const float* Kp = g_K + (size_t)bh * T_ * DK_;
    const float* Vp = g_V + (size_t)bh * T_ * DK_;

    const float tau   = g_tau[b];
    const float scale = 0.125f / tau;

    float q[64];
    {
        const float4* q4 = (const float4*)(Qp + (size_t)tid * DK_);
#pragma unroll
        for (int i = 0; i < 16; i++) {
            float4 v = q4[i];
            q[4*i+0] = v.x; q[4*i+1] = v.y; q[4*i+2] = v.z; q[4*i+3] = v.w;
        }
    }

    float o[64];
#pragma unroll
    for (int d = 0; d < 64; d++) o[d] = 0.f;
    float m = -1e30f, l = 0.f;

    for (int kt = 0; kt < T_ / 64; kt++) {
        {
            const float4* kg = (const float4*)(Kp + (size_t)kt * 64 * DK_);
            const float4* vg = (const float4*)(Vp + (size_t)kt * 64 * DK_);
            float4* ks4 = (float4*)Ks;
            float4* vs4 = (float4*)Vs;
#pragma unroll
            for (int i = 0; i < 8; i++) {
                ks4[tid + i*128] = kg[tid + i*128];
                vs4[tid + i*128] = vg[tid + i*128];
            }
        }
        __syncthreads();

#pragma unroll 2
        for (int kk = 0; kk < 64; kk++) {
            const float4* k4 = (const float4*)(Ks + kk * 64);
            float s = 0.f;
#pragma unroll
            for (int i = 0; i < 16; i++) {
                float4 kv = k4[i];
                s += q[4*i+0]*kv.x + q[4*i+1]*kv.y + q[4*i+2]*kv.z + q[4*i+3]*kv.w;
            }
            s *= scale;
            if (s > m) {
                const float corr = __expf(m - s);
                m = s;
                l *= corr;
#pragma unroll
                for (int d = 0; d < 64; d++) o[d] *= corr;
            }
            const float p = __expf(s - m);
            l += p;
            const float4* v4 = (const float4*)(Vs + kk * 64);
#pragma unroll
            for (int i = 0; i < 16; i++) {
                float4 vv = v4[i];
                o[4*i+0] += p * vv.x;
                o[4*i+1] += p * vv.y;
                o[4*i+2] += p * vv.z;
                o[4*i+3] += p * vv.w;
            }
        }
        __syncthreads();
    }

    const float c    = g_c[b];
    const float cl   = c / l;
    const float omc  = 1.0f - c;
    const float* vm  = g_vmean + bh * DK_;
    float* outp = g_attn + ((size_t)(b * T_) + q0 + tid) * D_ + h * DK_;
    float4* out4 = (float4*)outp;
#pragma unroll
    for (int i = 0; i < 16; i++) {
        float4 r;
        r.x = o[4*i+0]*cl + omc*vm[4*i+0];
        r.y = o[4*i+1]*cl + omc*vm[4*i+1];
        r.z = o[4*i+2]*cl + omc*vm[4*i+2];
        r.w = o[4*i+3]*cl + omc*vm[4*i+3];
        out4[i] = r;
    }
}

// ---------------- launch ----------------
extern "C" void kernel_launch(void* const* d_in, const int* in_sizes, int n_in,
                              void* d_out, int out_size)
{
    const float* x   = (const float*)d_in[0];
    const float* Wq  = (const float*)d_in[1];
    const float* bq  = (const float*)d_in[2];
    const float* Wk  = (const float*)d_in[3];
    const float* bk  = (const float*)d_in[4];
    const float* Wv  = (const float*)d_in[5];
    const float* bv  = (const float*)d_in[6];
    const float* Wo  = (const float*)d_in[7];
    const float* bo  = (const float*)d_in[8];
    const float* Wg1 = (const float*)d_in[9];
    const float* bg1 = (const float*)d_in[10];
    const float* Wg2 = (const float*)d_in[11];
    const float* bg2 = (const float*)d_in[12];
    float* out = (float*)d_out;

    float *pQ, *pK, *pV, *pAttn;
    cudaGetSymbolAddress((void**)&pQ,    g_Q);
    cudaGetSymbolAddress((void**)&pK,    g_K);
    cudaGetSymbolAddress((void**)&pV,    g_V);
    cudaGetSymbolAddress((void**)&pAttn, g_attn);

    const int M = B_ * T_, N = D_, K = D_;
    dim3 gemm_grid(N / 128, M / 128);   // (8, 32)

    gemm_tf32<1><<<gemm_grid, 256>>>(x, Wq, bq, pQ, M, N, K);
    gemm_tf32<1><<<gemm_grid, 256>>>(x, Wk, bk, pK, M, N, K);
    gemm_tf32<1><<<gemm_grid, 256>>>(x, Wv, bv, pV, M, N, K);

    float* u_out = (out_size >= BTD + B_) ? (out + (out_size - B_)) : nullptr;
    gate_kernel<<<B_, 256>>>(Wg1, bg1, Wg2, bg2, u_out);

    vmean_kernel<<<B_ * H_, DK_>>>();

    dim3 attn_grid(B_ * H_, T_ / 128);
    flash_attn_kernel<<<attn_grid, 128>>>(); 

    gemm_tf32<0><<<gemm_grid, 256>>>(pAttn, Wo, bo, out, M, N, K);
}